// round 7
// baseline (speedup 1.0000x reference)
#include <cuda_runtime.h>
#include <cstdint>
#include <cub/cub.cuh>

// ---------------------------------------------------------------------------
// ProposalLayer: B=4, A=9, H=50, W=76, FEAT_STRIDE=16
// pre-NMS topN = 6000, post-NMS topN = 300, nms thresh = 0.7
// ---------------------------------------------------------------------------

#define BATCH     4
#define A_NUM     9
#define H_DIM     50
#define W_DIM     76
#define HW_DIM    (H_DIM * W_DIM)          // 3800
#define N_ANCH    (A_NUM * HW_DIM)         // 34200
#define TOTAL     (BATCH * N_ANCH)         // 136800
#define PRE_TOPN  6000
#define POST_TOPN 300
#define NMS_TH    0.7f
#define NWORDS    94                        // ceil(6000/64)
#define TAIL_BITS 48                        // 6000 - 93*64
#define NONE_IDX  0x7FFFFFFFu

typedef unsigned long long u64;

// Precomputed generate_anchors(base=16, ratios={0.5,1,2}, scales={8,16,32})
__constant__ float c_anchors[A_NUM * 4] = {
    -84.f,  -40.f,   99.f,   55.f,
   -176.f,  -88.f,  191.f,  103.f,
   -360.f, -184.f,  375.f,  199.f,
    -56.f,  -56.f,   71.f,   71.f,
   -120.f, -120.f,  135.f,  135.f,
   -248.f, -248.f,  263.f,  263.f,
    -36.f,  -80.f,   51.f,   95.f,
    -80.f, -168.f,   95.f,  183.f,
   -168.f, -344.f,  183.f,  359.f
};

// Device-global scratch (no runtime allocation allowed)
__device__ u64    g_keys_in [TOTAL];
__device__ u64    g_keys_out[TOTAL];
__device__ float4 g_boxes   [TOTAL];
__device__ float4 g_sboxes  [BATCH][PRE_TOPN];
__device__ float  g_sareas  [BATCH][PRE_TOPN];
__device__ u64    g_mask    [BATCH][PRE_TOPN][NWORDS];
__device__ unsigned char g_cub_temp[8 << 20];

// ---------------------------------------------------------------------------
// Kernel 1: decode + clip boxes, build packed sort keys.
// Scores are uniform [0,1): float bits u <= 0x3F7FFFFF (30 bits). Key =
// [b:2 @46 | (0x3F7FFFFF-u):30 @16 | idx:16 @0]. Ascending stable radix on
// bits [16,48) (exactly 32 bits -> 4 onesweep passes) gives (b asc, score
// desc, ties index-asc) == stable argsort(-sc).
// ---------------------------------------------------------------------------
__global__ void decode_kernel(const float* __restrict__ scores,
                              const float* __restrict__ deltas,
                              const float* __restrict__ im_info)
{
    int t = blockIdx.x * blockDim.x + threadIdx.x;
    if (t >= TOTAL) return;

    int w  = t % W_DIM;
    int h  = (t / W_DIM) % H_DIM;
    int a  = (t / HW_DIM) % A_NUM;
    int b  = t / N_ANCH;
    int hw = h * W_DIM + w;

    float sx = (float)(w * 16);
    float sy = (float)(h * 16);
    float ax1 = c_anchors[a * 4 + 0] + sx;
    float ay1 = c_anchors[a * 4 + 1] + sy;
    float ax2 = c_anchors[a * 4 + 2] + sx;
    float ay2 = c_anchors[a * 4 + 3] + sy;

    float wa  = ax2 - ax1 + 1.0f;
    float ha  = ay2 - ay1 + 1.0f;
    float cxa = ax1 + 0.5f * wa;
    float cya = ay1 + 0.5f * ha;

    size_t dbase = ((size_t)b * 4 * A_NUM + (size_t)a * 4) * HW_DIM + hw;
    float dx = deltas[dbase];
    float dy = deltas[dbase +     HW_DIM];
    float dw = deltas[dbase + 2 * HW_DIM];
    float dh = deltas[dbase + 3 * HW_DIM];

    float pcx = dx * wa + cxa;
    float pcy = dy * ha + cya;
    float pw  = expf(dw) * wa;
    float ph  = expf(dh) * ha;

    float imh = im_info[b * 3 + 0];
    float imw = im_info[b * 3 + 1];

    float x1 = fminf(fmaxf(pcx - 0.5f * pw, 0.0f), imw - 1.0f);
    float y1 = fminf(fmaxf(pcy - 0.5f * ph, 0.0f), imh - 1.0f);
    float x2 = fminf(fmaxf(pcx + 0.5f * pw, 0.0f), imw - 1.0f);
    float y2 = fminf(fmaxf(pcy + 0.5f * ph, 0.0f), imh - 1.0f);

    int i = hw * A_NUM + a;   // reference flattening: ((h*W + w)*A + a)
    g_boxes[(size_t)b * N_ANCH + i] = make_float4(x1, y1, x2, y2);

    float sc = scores[((size_t)b * 2 * A_NUM + A_NUM + a) * HW_DIM + hw];
    unsigned u = __float_as_uint(sc);            // in [0, 0x3F7FFFFF]
    u = min(u, 0x3F7FFFFFu);                     // safety clamp
    unsigned desc30 = 0x3F7FFFFFu - u;           // ascending == score desc
    g_keys_in[(size_t)b * N_ANCH + i] =
        ((u64)(unsigned)b << 46) | ((u64)desc30 << 16) | (u64)(unsigned)i;
}

// ---------------------------------------------------------------------------
// Kernel 2: gather top-6000 sorted boxes + areas per image.
// ---------------------------------------------------------------------------
__global__ void gather_kernel(const u64* __restrict__ keys)
{
    int t = blockIdx.x * blockDim.x + threadIdx.x;
    if (t >= BATCH * PRE_TOPN) return;
    int b = t / PRE_TOPN;
    int j = t % PRE_TOPN;
    unsigned idx = (unsigned)(keys[(size_t)b * N_ANCH + j] & 0xFFFFull);
    float4 v = g_boxes[(size_t)b * N_ANCH + idx];
    g_sboxes[b][j] = v;
    g_sareas[b][j] = (v.z - v.x + 1.0f) * (v.w - v.y + 1.0f);
}

// ---------------------------------------------------------------------------
// Kernel 3: suppression bitmask, 64-row x 256-col tiles, 256 threads/block.
// Thread t -> row i = bi*64 + (t>>2), word bj = cj*4 + (t&3): computes the
// 64-bit word of columns [bj*64, bj*64+64), bit c set iff IoU(i,j) > 0.7,
// j > i. Grid 94 x 25 x 4 with diagonal culling (vs 94x94x4 of 64-thr blocks).
// Multiply-form IoU with 1e-5 relative guard band; exact division fallback
// inside the band (decision-identical to reference).
// ---------------------------------------------------------------------------
__global__ void mask_kernel()
{
    int bi = blockIdx.x, cj = blockIdx.y, b = blockIdx.z;
    int j_base = cj << 8;                    // cj * 256
    if (j_base + 255 <= (bi << 6)) return;   // tile entirely at/below diagonal

    __shared__ float4 cb[256];
    __shared__ float  ca[256];
    int t  = threadIdx.x;
    int jt = j_base + t;
    if (jt < PRE_TOPN) { cb[t] = g_sboxes[b][jt]; ca[t] = g_sareas[b][jt]; }
    __syncthreads();

    int i  = (bi << 6) + (t >> 2);
    if (i >= PRE_TOPN) return;
    int bj = (cj << 2) + (t & 3);
    if (bj >= NWORDS || bj < (i >> 6)) return;   // word never read by reduce

    float4 bx = g_sboxes[b][i];
    float  ai = g_sareas[b][i];

    u64 bits = 0;
    int j0w  = bj << 6;
    int cl0  = (t & 3) << 6;                 // smem offset of this word's cols
    #pragma unroll 4
    for (int c = 0; c < 64; c++) {
        int j = j0w + c;
        if (j <= i || j >= PRE_TOPN) continue;
        float4 bv = cb[cl0 + c];
        float iw = fminf(bx.z, bv.z) - fmaxf(bx.x, bv.x) + 1.0f;
        float ih = fminf(bx.w, bv.w) - fmaxf(bx.y, bv.y) + 1.0f;
        float inter = fmaxf(iw, 0.0f) * fmaxf(ih, 0.0f);
        float u  = ai + ca[cl0 + c] - inter;
        float diff = inter - NMS_TH * u;
        bool sup;
        if (fabsf(diff) > 1e-5f * u) sup = (diff > 0.0f);       // fast path
        else                         sup = (inter / u) > NMS_TH; // exact (rare)
        if (sup) bits |= (1ull << c);
    }
    g_mask[b][i][bj] = bits;
}

// ---------------------------------------------------------------------------
// Kernel 4: greedy reduce — ONE WARP per image, barrier-free.
// removed-bitmask in registers (lane l owns words 3l..3l+2). Next-kept search
// = per-lane ffs + one REDUX (__reduce_min_sync) instead of a 4-SHFL chain.
// Finds first THREE alive (j1 definitive, j2/j3 speculative) so each mask row
// is ~2 iterations in flight before its fold (covers L2 latency). Box emit is
// deferred: kept indices go to SMEM; boxes gathered/written in parallel after
// the loop (no GMEM loads/stores on the serial path).
// ---------------------------------------------------------------------------
__global__ void __launch_bounds__(32, 1)
reduce_kernel(float* __restrict__ out)
{
    const unsigned FULL = 0xFFFFFFFFu;
    int b = blockIdx.x;
    int l = threadIdx.x;
    __shared__ short s_kept[POST_TOPN];

    // validity masks for owned words
    u64 vm[3];
    #pragma unroll
    for (int s = 0; s < 3; s++) {
        int w = 3 * l + s;
        vm[s] = (w < NWORDS - 1) ? ~0ull
              : (w == NWORDS - 1 ? ((1ull << TAIL_BITS) - 1ull) : 0ull);
    }
    u64 removed[3] = {0, 0, 0};

    // Pre-fill output rows: [b, 0,0,0,0] (d_out arrives poisoned).
    for (int j = l; j < POST_TOPN * 5; j += 32) {
        int r = j / 5, c = j % 5;
        out[((size_t)b * POST_TOPN + r) * 5 + c] = (c == 0) ? (float)b : 0.0f;
    }

    const u64* maskb = &g_mask[b][0][0];

    auto load_row = [&](int j, u64* r) {
        int wlo = j >> 6;
        const u64* rp = maskb + (size_t)j * NWORDS;
        #pragma unroll
        for (int s = 0; s < 3; s++) {
            int w = 3 * l + s;
            r[s] = (w < NWORDS && w >= wlo) ? rp[w] : 0ull;
        }
    };
    // lowest set bit among this lane's words (NONE_IDX if empty)
    auto lane_first = [&](u64 a0, u64 a1, u64 a2) -> unsigned {
        unsigned base = (unsigned)(3 * l) << 6;
        if (a0) return base       + (unsigned)(__ffsll((long long)a0) - 1);
        if (a1) return base + 64  + (unsigned)(__ffsll((long long)a1) - 1);
        if (a2) return base + 128 + (unsigned)(__ffsll((long long)a2) - 1);
        return NONE_IDX;
    };
    auto clear_bit = [&](unsigned j, u64& a0, u64& a1, u64& a2) {
        int s = (int)(j >> 6) - 3 * l;
        u64 m = 1ull << (j & 63);
        if (s == 0) a0 &= ~m; else if (s == 1) a1 &= ~m;
        else if (s == 2) a2 &= ~m;
    };

    // bootstrap: candidate 0 is always the first kept box
    int i = 0;
    u64 row[3];
    load_row(0, row);
    int idxA = -1, idxB = -1;            // speculated next / next-next rows
    u64 bufA[3] = {0,0,0}, bufB[3] = {0,0,0};

    int count = 0;
    while (true) {
        if (l == 0) s_kept[count] = (short)i;
        count++;
        if (count == POST_TOPN) break;

        // fold suppression row of i; mark i itself removed
        removed[0] |= row[0];
        removed[1] |= row[1];
        removed[2] |= row[2];
        {
            int s = (i >> 6) - 3 * l;
            if (s >= 0 && s < 3) removed[s] |= 1ull << (i & 63);
        }

        u64 a0 = ~removed[0] & vm[0];
        u64 a1 = ~removed[1] & vm[1];
        u64 a2 = ~removed[2] & vm[2];

        unsigned j1 = __reduce_min_sync(FULL, lane_first(a0, a1, a2));
        if (j1 == NONE_IDX) break;
        clear_bit(j1, a0, a1, a2);
        unsigned j2 = __reduce_min_sync(FULL, lane_first(a0, a1, a2));
        unsigned j3 = NONE_IDX;
        if (j2 != NONE_IDX) {
            clear_bit(j2, a0, a1, a2);
            j3 = __reduce_min_sync(FULL, lane_first(a0, a1, a2));
        }

        // row for j1: promoted from speculation (usual) or fresh load (rare)
        u64 nr[3];
        if ((int)j1 == idxA)      { nr[0]=bufA[0]; nr[1]=bufA[1]; nr[2]=bufA[2]; }
        else if ((int)j1 == idxB) { nr[0]=bufB[0]; nr[1]=bufB[1]; nr[2]=bufB[2]; }
        else                      load_row((int)j1, nr);

        // new bufA <- row(j2): usually promoted from old bufB
        u64 nA[3]; int nidxA = -1;
        if (j2 != NONE_IDX) {
            if ((int)j2 == idxB) { nA[0]=bufB[0]; nA[1]=bufB[1]; nA[2]=bufB[2]; }
            else                 load_row((int)j2, nA);
            nidxA = (int)j2;
        } else { nA[0]=nA[1]=nA[2]=0; }

        // new bufB <- row(j3): fresh speculative load
        u64 nB[3]; int nidxB = -1;
        if (j3 != NONE_IDX) { load_row((int)j3, nB); nidxB = (int)j3; }
        else { nB[0]=nB[1]=nB[2]=0; }

        i = (int)j1;
        row[0]=nr[0]; row[1]=nr[1]; row[2]=nr[2];
        bufA[0]=nA[0]; bufA[1]=nA[1]; bufA[2]=nA[2]; idxA = nidxA;
        bufB[0]=nB[0]; bufB[1]=nB[1]; bufB[2]=nB[2]; idxB = nidxB;
    }

    // parallel deferred emit of kept boxes (MLP-friendly gather)
    __syncwarp();
    for (int k = l; k < count; k += 32) {
        int idx = s_kept[k];
        float4 v = g_sboxes[b][idx];
        float* o = out + ((size_t)b * POST_TOPN + k) * 5;
        o[1] = v.x; o[2] = v.y; o[3] = v.z; o[4] = v.w;
    }
}

// ---------------------------------------------------------------------------
// Launch
// ---------------------------------------------------------------------------
extern "C" void kernel_launch(void* const* d_in, const int* in_sizes, int n_in,
                              void* d_out, int out_size)
{
    const float* scores  = (const float*)d_in[0];   // (4, 18, 50, 76)
    const float* deltas  = (const float*)d_in[1];   // (4, 36, 50, 76)
    const float* im_info = (const float*)d_in[2];   // (4, 3)
    float*       out     = (float*)d_out;           // (4, 300, 5)

    void *keys_in_p, *keys_out_p, *temp_p;
    cudaGetSymbolAddress(&keys_in_p,  g_keys_in);
    cudaGetSymbolAddress(&keys_out_p, g_keys_out);
    cudaGetSymbolAddress(&temp_p,     g_cub_temp);

    decode_kernel<<<(TOTAL + 255) / 256, 256>>>(scores, deltas, im_info);

    // One chip-wide stable radix sort: bits [16,48) = (b, score desc), 4 passes.
    size_t temp_bytes = 0;
    cub::DeviceRadixSort::SortKeys(
        nullptr, temp_bytes,
        (const u64*)keys_in_p, (u64*)keys_out_p, TOTAL, 16, 48);
    if (temp_bytes > (size_t)(8 << 20)) temp_bytes = (size_t)(8 << 20);
    cub::DeviceRadixSort::SortKeys(
        temp_p, temp_bytes,
        (const u64*)keys_in_p, (u64*)keys_out_p, TOTAL, 16, 48);

    gather_kernel<<<(BATCH * PRE_TOPN + 255) / 256, 256>>>((const u64*)keys_out_p);

    dim3 mgrid(NWORDS, (PRE_TOPN + 255) / 256 + 1, BATCH);   // 94 x 25 x 4
    mask_kernel<<<mgrid, 256>>>();

    reduce_kernel<<<BATCH, 32>>>(out);
}

// round 8
// speedup vs baseline: 1.2921x; 1.2921x over previous
#include <cuda_runtime.h>
#include <cstdint>
#include <cub/cub.cuh>

// ---------------------------------------------------------------------------
// ProposalLayer: B=4, A=9, H=50, W=76, FEAT_STRIDE=16
// pre-NMS topN = 6000, post-NMS topN = 300, nms thresh = 0.7
// R8 = R5 structure (best known: 391us) with ONE change: 30-bit score key ->
// 4-pass onesweep sort instead of 5 (bits [16,48)).
// ---------------------------------------------------------------------------

#define BATCH     4
#define A_NUM     9
#define H_DIM     50
#define W_DIM     76
#define HW_DIM    (H_DIM * W_DIM)          // 3800
#define N_ANCH    (A_NUM * HW_DIM)         // 34200
#define TOTAL     (BATCH * N_ANCH)         // 136800
#define PRE_TOPN  6000
#define POST_TOPN 300
#define NMS_TH    0.7f
#define NWORDS    94                        // ceil(6000/64)
#define TAIL_BITS 48                        // 6000 - 93*64

typedef unsigned long long u64;

// Precomputed generate_anchors(base=16, ratios={0.5,1,2}, scales={8,16,32})
__constant__ float c_anchors[A_NUM * 4] = {
    -84.f,  -40.f,   99.f,   55.f,
   -176.f,  -88.f,  191.f,  103.f,
   -360.f, -184.f,  375.f,  199.f,
    -56.f,  -56.f,   71.f,   71.f,
   -120.f, -120.f,  135.f,  135.f,
   -248.f, -248.f,  263.f,  263.f,
    -36.f,  -80.f,   51.f,   95.f,
    -80.f, -168.f,   95.f,  183.f,
   -168.f, -344.f,  183.f,  359.f
};

// Device-global scratch (no runtime allocation allowed)
__device__ u64    g_keys_in [TOTAL];
__device__ u64    g_keys_out[TOTAL];
__device__ float4 g_boxes   [TOTAL];
__device__ float4 g_sboxes  [BATCH][PRE_TOPN];
__device__ float  g_sareas  [BATCH][PRE_TOPN];
__device__ u64    g_mask    [BATCH][PRE_TOPN][NWORDS];
__device__ unsigned char g_cub_temp[8 << 20];

// ---------------------------------------------------------------------------
// Kernel 1: decode + clip boxes, build packed sort keys.
// Scores are uniform [0,1): float bits u <= 0x3F7FFFFF (30 bits). Key =
// [b:2 @46 | (0x3F7FFFFF-u):30 @16 | idx:16 @0]. Ascending stable radix on
// bits [16,48) (exactly 32 bits -> 4 onesweep passes) gives (b asc, score
// desc, ties index-asc) == stable argsort(-sc).
// ---------------------------------------------------------------------------
__global__ void decode_kernel(const float* __restrict__ scores,
                              const float* __restrict__ deltas,
                              const float* __restrict__ im_info)
{
    int t = blockIdx.x * blockDim.x + threadIdx.x;
    if (t >= TOTAL) return;

    int w  = t % W_DIM;
    int h  = (t / W_DIM) % H_DIM;
    int a  = (t / HW_DIM) % A_NUM;
    int b  = t / N_ANCH;
    int hw = h * W_DIM + w;

    float sx = (float)(w * 16);
    float sy = (float)(h * 16);
    float ax1 = c_anchors[a * 4 + 0] + sx;
    float ay1 = c_anchors[a * 4 + 1] + sy;
    float ax2 = c_anchors[a * 4 + 2] + sx;
    float ay2 = c_anchors[a * 4 + 3] + sy;

    float wa  = ax2 - ax1 + 1.0f;
    float ha  = ay2 - ay1 + 1.0f;
    float cxa = ax1 + 0.5f * wa;
    float cya = ay1 + 0.5f * ha;

    size_t dbase = ((size_t)b * 4 * A_NUM + (size_t)a * 4) * HW_DIM + hw;
    float dx = deltas[dbase];
    float dy = deltas[dbase +     HW_DIM];
    float dw = deltas[dbase + 2 * HW_DIM];
    float dh = deltas[dbase + 3 * HW_DIM];

    float pcx = dx * wa + cxa;
    float pcy = dy * ha + cya;
    float pw  = expf(dw) * wa;
    float ph  = expf(dh) * ha;

    float imh = im_info[b * 3 + 0];
    float imw = im_info[b * 3 + 1];

    float x1 = fminf(fmaxf(pcx - 0.5f * pw, 0.0f), imw - 1.0f);
    float y1 = fminf(fmaxf(pcy - 0.5f * ph, 0.0f), imh - 1.0f);
    float x2 = fminf(fmaxf(pcx + 0.5f * pw, 0.0f), imw - 1.0f);
    float y2 = fminf(fmaxf(pcy + 0.5f * ph, 0.0f), imh - 1.0f);

    int i = hw * A_NUM + a;   // reference flattening: ((h*W + w)*A + a)
    g_boxes[(size_t)b * N_ANCH + i] = make_float4(x1, y1, x2, y2);

    float sc = scores[((size_t)b * 2 * A_NUM + A_NUM + a) * HW_DIM + hw];
    unsigned u = __float_as_uint(sc);            // in [0, 0x3F7FFFFF]
    u = min(u, 0x3F7FFFFFu);                     // safety clamp
    unsigned desc30 = 0x3F7FFFFFu - u;           // ascending == score desc
    g_keys_in[(size_t)b * N_ANCH + i] =
        ((u64)(unsigned)b << 46) | ((u64)desc30 << 16) | (u64)(unsigned)i;
}

// ---------------------------------------------------------------------------
// Kernel 2: gather top-6000 sorted boxes + areas per image.
// ---------------------------------------------------------------------------
__global__ void gather_kernel(const u64* __restrict__ keys)
{
    int t = blockIdx.x * blockDim.x + threadIdx.x;
    if (t >= BATCH * PRE_TOPN) return;
    int b = t / PRE_TOPN;
    int j = t % PRE_TOPN;
    unsigned idx = (unsigned)(keys[(size_t)b * N_ANCH + j] & 0xFFFFull);
    float4 v = g_boxes[(size_t)b * N_ANCH + idx];
    g_sboxes[b][j] = v;
    g_sareas[b][j] = (v.z - v.x + 1.0f) * (v.w - v.y + 1.0f);
}

// ---------------------------------------------------------------------------
// Kernel 3: suppression bitmask matrix (upper triangle only).  [R5 version]
// Block (bi, bj, b): thread t owns row i = bi*64+t, computes the 64-bit word
// of columns [bj*64, bj*64+64): bit c set iff IoU(i,j) > 0.7 and j > i.
// Multiply-form test with 1e-5 relative guard band; exact division fallback
// inside the band (decision-identical to reference).
// ---------------------------------------------------------------------------
__global__ void mask_kernel()
{
    int bi = blockIdx.x, bj = blockIdx.y, b = blockIdx.z;
    if (bj < bi) return;

    __shared__ float4 cb[64];
    __shared__ float  ca[64];
    int t  = threadIdx.x;
    int j0 = bj * 64;
    int jt = j0 + t;
    if (jt < PRE_TOPN) { cb[t] = g_sboxes[b][jt]; ca[t] = g_sareas[b][jt]; }
    __syncthreads();

    int i = bi * 64 + t;
    if (i >= PRE_TOPN) return;
    float4 bx = g_sboxes[b][i];
    float  ai = g_sareas[b][i];

    u64 bits = 0;
    int cmax = min(64, PRE_TOPN - j0);
    #pragma unroll 4
    for (int c = 0; c < cmax; c++) {
        int j = j0 + c;
        if (j <= i) continue;
        float4 bv = cb[c];
        float iw = fminf(bx.z, bv.z) - fmaxf(bx.x, bv.x) + 1.0f;
        float ih = fminf(bx.w, bv.w) - fmaxf(bx.y, bv.y) + 1.0f;
        float inter = fmaxf(iw, 0.0f) * fmaxf(ih, 0.0f);
        float u  = ai + ca[c] - inter;
        float diff = inter - NMS_TH * u;
        bool sup;
        if (fabsf(diff) > 1e-5f * u) sup = (diff > 0.0f);       // fast path
        else                         sup = (inter / u) > NMS_TH; // exact (rare)
        if (sup) bits |= (1ull << c);
    }
    g_mask[b][i][bj] = bits;
}

// ---------------------------------------------------------------------------
// Kernel 4: greedy reduce — ONE WARP per image, barrier-free.  [R5 version]
// removed-bitmask lives in registers (3 x u64 per lane; lane l owns words
// 3l, 3l+1, 3l+2). Kept bits are also marked removed, so the next kept box is
// simply the first zero bit. Mask rows are software-pipelined: after ORing
// row i, the next kept j1 is definitive and j2 is a ~99.7%-probability
// speculation, so row j1 is always >=1 iteration in flight (usually 2).
// ---------------------------------------------------------------------------
__global__ void __launch_bounds__(32, 1)
reduce_kernel(float* __restrict__ out)
{
    const unsigned FULL = 0xFFFFFFFFu;
    int b = blockIdx.x;
    int l = threadIdx.x;

    // validity masks for owned words
    u64 vm[3];
    #pragma unroll
    for (int s = 0; s < 3; s++) {
        int w = 3 * l + s;
        vm[s] = (w < NWORDS - 1) ? ~0ull
              : (w == NWORDS - 1 ? ((1ull << TAIL_BITS) - 1ull) : 0ull);
    }
    u64 removed[3] = {0, 0, 0};

    // Pre-fill output rows: [b, 0,0,0,0] (d_out arrives poisoned).
    for (int j = l; j < POST_TOPN * 5; j += 32) {
        int r = j / 5, c = j % 5;
        out[((size_t)b * POST_TOPN + r) * 5 + c] = (c == 0) ? (float)b : 0.0f;
    }

    const u64* maskb = &g_mask[b][0][0];

    // load row j, zeroed below its diagonal word and outside [0,NWORDS)
    auto load_row = [&](int j, u64* r) {
        int wlo = j >> 6;
        const u64* rp = maskb + (size_t)j * NWORDS;
        #pragma unroll
        for (int s = 0; s < 3; s++) {
            int w = 3 * l + s;
            r[s] = (w < NWORDS && w >= wlo) ? rp[w] : 0ull;
        }
    };
    // first zero bit of (removed | ~vm); all lanes return the same value
    auto find_first = [&](u64 a0, u64 a1, u64 a2) -> int {
        int fs = a0 ? 0 : (a1 ? 1 : (a2 ? 2 : 3));
        unsigned ball = __ballot_sync(FULL, fs < 3);
        if (!ball) return -1;
        int L   = __ffs(ball) - 1;
        int fsL = __shfl_sync(FULL, fs, L);
        u64 w0 = __shfl_sync(FULL, a0, L);
        u64 w1 = __shfl_sync(FULL, a1, L);
        u64 w2 = __shfl_sync(FULL, a2, L);
        u64 fa = (fsL == 0) ? w0 : ((fsL == 1) ? w1 : w2);
        return (L * 3 + fsL) * 64 + __ffsll((long long)fa) - 1;
    };

    // bootstrap: candidate 0 is always the first kept box
    int i = 0;
    u64 row[3];
    load_row(0, row);
    float4 pb = g_sboxes[b][0];     // broadcast load
    int idx2 = -1;
    u64 spec[3] = {0, 0, 0};

    int count = 0;
    while (true) {
        // emit current kept box
        if (l == 0) {
            float* o = out + ((size_t)b * POST_TOPN + count) * 5;
            o[1] = pb.x; o[2] = pb.y; o[3] = pb.z; o[4] = pb.w;
        }
        count++;
        if (count == POST_TOPN) break;

        // fold suppression row of i, mark i itself removed
        removed[0] |= row[0];
        removed[1] |= row[1];
        removed[2] |= row[2];
        int wi = i >> 6;
        int sl = wi - 3 * l;
        if (sl >= 0 && sl < 3) removed[sl] |= 1ull << (i & 63);

        // j1 = definitive next kept; j2 = speculative next-next
        u64 a0 = ~removed[0] & vm[0];
        u64 a1 = ~removed[1] & vm[1];
        u64 a2 = ~removed[2] & vm[2];
        int j1 = find_first(a0, a1, a2);
        if (j1 < 0) break;
        int s1 = (j1 >> 6) - 3 * l;
        u64 bm = 1ull << (j1 & 63);
        if (s1 == 0) a0 &= ~bm; else if (s1 == 1) a1 &= ~bm;
        else if (s1 == 2) a2 &= ~bm;
        int j2 = find_first(a0, a1, a2);

        // row for j1: promoted from speculation (usual) or fresh load (rare)
        u64 nrow[3];
        if (j1 == idx2) {
            nrow[0] = spec[0]; nrow[1] = spec[1]; nrow[2] = spec[2];
        } else {
            load_row(j1, nrow);
        }
        float4 npb = g_sboxes[b][j1];          // box prefetch (always exact)

        // issue speculative load for j2
        if (j2 >= 0) { load_row(j2, spec); idx2 = j2; }
        else idx2 = -1;

        i = j1;
        row[0] = nrow[0]; row[1] = nrow[1]; row[2] = nrow[2];
        pb = npb;
    }
}

// ---------------------------------------------------------------------------
// Launch
// ---------------------------------------------------------------------------
extern "C" void kernel_launch(void* const* d_in, const int* in_sizes, int n_in,
                              void* d_out, int out_size)
{
    const float* scores  = (const float*)d_in[0];   // (4, 18, 50, 76)
    const float* deltas  = (const float*)d_in[1];   // (4, 36, 50, 76)
    const float* im_info = (const float*)d_in[2];   // (4, 3)
    float*       out     = (float*)d_out;           // (4, 300, 5)

    void *keys_in_p, *keys_out_p, *temp_p;
    cudaGetSymbolAddress(&keys_in_p,  g_keys_in);
    cudaGetSymbolAddress(&keys_out_p, g_keys_out);
    cudaGetSymbolAddress(&temp_p,     g_cub_temp);

    decode_kernel<<<(TOTAL + 255) / 256, 256>>>(scores, deltas, im_info);

    // One chip-wide stable radix sort: bits [16,48) = (b, score desc), 4 passes.
    size_t temp_bytes = 0;
    cub::DeviceRadixSort::SortKeys(
        nullptr, temp_bytes,
        (const u64*)keys_in_p, (u64*)keys_out_p, TOTAL, 16, 48);
    if (temp_bytes > (size_t)(8 << 20)) temp_bytes = (size_t)(8 << 20);
    cub::DeviceRadixSort::SortKeys(
        temp_p, temp_bytes,
        (const u64*)keys_in_p, (u64*)keys_out_p, TOTAL, 16, 48);

    gather_kernel<<<(BATCH * PRE_TOPN + 255) / 256, 256>>>((const u64*)keys_out_p);

    dim3 mgrid(NWORDS, NWORDS, BATCH);
    mask_kernel<<<mgrid, 64>>>();

    reduce_kernel<<<BATCH, 32>>>(out);
}